// round 15
// baseline (speedup 1.0000x reference)
#include <cuda_runtime.h>
#include <cuda_bf16.h>
#include <math.h>
#include <stdint.h>

#define N_NODES 50000
#define T_STEPS 24
#define E_EDGES 800000
#define NT_ROWS (N_NODES * T_STEPS)

typedef unsigned long long ull;

// ---------------- packed helpers ---------------------------------------------
__device__ __forceinline__ ull ffma2(ull a, ull b, ull c) {
    ull d;
    asm("fma.rn.f32x2 %0, %1, %2, %3;" : "=l"(d) : "l"(a), "l"(b), "l"(c));
    return d;
}
__device__ __forceinline__ ull dup2f(float x) {
    ull r; asm("mov.b64 %0, {%1, %1};" : "=l"(r) : "f"(x)); return r;
}
__device__ __forceinline__ ull pack2f(float x, float y) {
    ull r; asm("mov.b64 %0, {%1, %2};" : "=l"(r) : "f"(x), "f"(y)); return r;
}
__device__ __forceinline__ float2 unpack2(ull v) {
    float2 r; asm("mov.b64 {%0, %1}, %2;" : "=f"(r.x), "=f"(r.y) : "l"(v)); return r;
}
__device__ __forceinline__ unsigned bf2pack(float x, float y) {
    __nv_bfloat162 b = __float22bfloat162_rn(make_float2(x, y));
    return *(unsigned*)&b;
}
__device__ __forceinline__ float2 bf2unpack(unsigned u) {
    __nv_bfloat162 b = *(__nv_bfloat162*)&u;
    return __bfloat1622float2(b);
}
__device__ __forceinline__ unsigned tf32r(float f) {
    unsigned u; asm("cvt.rna.tf32.f32 %0, %1;" : "=r"(u) : "f"(f)); return u;
}
// fast sigmoid/tanh: ex2.approx + rcp.approx (rel err ~1e-6)
__device__ __forceinline__ float sigf(float x) {
    float e, r;
    asm("ex2.approx.f32 %0, %1;" : "=f"(e) : "f"(-1.442695041f * x));
    asm("rcp.approx.f32 %0, %1;" : "=f"(r) : "f"(1.0f + e));
    return r;
}
__device__ __forceinline__ float tanhfast(float x) {
    return fmaf(2.0f, sigf(2.0f * x), -1.0f);
}

// ---------------- scratch (device globals) ----------------------------------
__device__ float g_sum[64];
__device__ float g_sumsq[64];
__device__ float g_bvec0[64];
__device__ float g_gbias[256];
__device__ unsigned g_Wg[256 * 64];     // tf32 bits of a*Wih, [g][k]
__device__ unsigned g_Whg[256 * 64];    // tf32 bits of Whh,   [g][k]
__device__ unsigned g_W0g[64 * 64];     // tf32 bits of a*W0,  [out][k]
__device__ float g_outnorm[N_NODES];
__device__ float g_innorm[N_NODES];
__device__ int   g_degout[N_NODES];
__device__ int   g_degin[N_NODES];
__device__ int   g_rowptr[N_NODES + 1];
__device__ int   g_cursor[N_NODES];
__device__ int   g_csrsrc[E_EDGES];
__device__ unsigned g_M1[T_STEPS * N_NODES * 32];
__device__ unsigned g_M2[T_STEPS * N_NODES * 32];
__device__ int   g_wq;
__device__ int   g_wqA;
__device__ int   g_wqB;

__device__ __forceinline__ float gelu_f(float x) {
    return 0.5f * x * (1.0f + erff(x * 0.70710678118654752440f));
}

// permuted k-slot within an 8-k block so (k, k+4) pairs are adjacent
__device__ __forceinline__ int kperm(int k) {   // k in 0..7
    return (k & 3) * 2 + (k >> 2);
}

// ---------------- init -------------------------------------------------------
__global__ void k_init(float* out, int out_n) {
    int i = blockIdx.x * blockDim.x + threadIdx.x;
    int stride = gridDim.x * blockDim.x;
    for (int j = i; j < out_n; j += stride) out[j] = 0.0f;
    for (int j = i; j < N_NODES; j += stride) { g_degout[j] = 0; g_degin[j] = 0; }
    if (i < 64) { g_sum[i] = 0.0f; g_sumsq[i] = 0.0f; }
    if (i == 0) { g_wq = 0; g_wqA = 0; g_wqB = 0; }
}

// ---------------- BN stats ---------------------------------------------------
__global__ void k_bnstats(const float4* __restrict__ h4) {
    __shared__ float ss[64], sq[64];
    int tid = threadIdx.x;
    if (tid < 64) { ss[tid] = 0.0f; sq[tid] = 0.0f; }
    __syncthreads();
    const int total4 = NT_ROWS * 16;
    float4 s = make_float4(0, 0, 0, 0);
    float4 q = make_float4(0, 0, 0, 0);
    for (int i = blockIdx.x * blockDim.x + tid; i < total4; i += gridDim.x * blockDim.x) {
        float4 v = h4[i];
        s.x += v.x; s.y += v.y; s.z += v.z; s.w += v.w;
        q.x += v.x * v.x; q.y += v.y * v.y; q.z += v.z * v.z; q.w += v.w * v.w;
    }
    int c = (tid & 15) * 4;
    atomicAdd(&ss[c + 0], s.x); atomicAdd(&ss[c + 1], s.y);
    atomicAdd(&ss[c + 2], s.z); atomicAdd(&ss[c + 3], s.w);
    atomicAdd(&sq[c + 0], q.x); atomicAdd(&sq[c + 1], q.y);
    atomicAdd(&sq[c + 2], q.z); atomicAdd(&sq[c + 3], q.w);
    __syncthreads();
    if (tid < 64) {
        atomicAdd(&g_sum[tid], ss[tid]);
        atomicAdd(&g_sumsq[tid], sq[tid]);
    }
}

// ---------------- merged prep ------------------------------------------------
__global__ void k_prepall(const float* __restrict__ gamma, const float* __restrict__ beta,
                          const float* __restrict__ W0,   const float* __restrict__ Wih,
                          const float* __restrict__ Whh,  const float* __restrict__ bih,
                          const float* __restrict__ bhh) {
    __shared__ float sa[64], sb[64];
    int tid = threadIdx.x;
    if (tid < 64) {
        float mu  = g_sum[tid]   * (1.0f / (float)NT_ROWS);
        float var = g_sumsq[tid] * (1.0f / (float)NT_ROWS) - mu * mu;
        float a = gamma[tid] * rsqrtf(var + 1e-5f);
        sa[tid] = a;
        sb[tid] = beta[tid] - mu * a;
    }
    __syncthreads();
    int b = blockIdx.x;
    if (b == 32) {
        for (int idx = tid; idx < 4096; idx += 256) {
            int out = idx >> 6, k = idx & 63;
            g_W0g[idx] = tf32r(sa[k] * W0[k * 64 + out]);
        }
        if (tid < 64) {
            float acc = 0.0f;
            for (int k = 0; k < 64; k++) acc += sb[k] * W0[k * 64 + tid];
            g_bvec0[tid] = acc;
        }
        {   // gate bias
            float acc = bih[tid] + bhh[tid];
            for (int k = 0; k < 64; k++) acc += sb[k] * Wih[tid * 64 + k];
            g_gbias[tid] = acc;
        }
    } else {
        for (int i = tid; i < 512; i += 256) {
            int idx = b * 512 + i;
            int g = idx >> 6, k = idx & 63;
            g_Wg[idx]  = tf32r(sa[k] * Wih[g * 64 + k]);
            g_Whg[idx] = tf32r(Whh[g * 64 + k]);
        }
    }
}

// ---------------- degrees / norms / CSR --------------------------------------
__global__ void k_deg(const int* __restrict__ src, const int* __restrict__ dst) {
    for (int e = blockIdx.x * blockDim.x + threadIdx.x; e < E_EDGES;
         e += gridDim.x * blockDim.x) {
        atomicAdd(&g_degout[src[e]], 1);
        atomicAdd(&g_degin[dst[e]], 1);
    }
}

__global__ void k_norm() {
    for (int n = blockIdx.x * blockDim.x + threadIdx.x; n < N_NODES;
         n += gridDim.x * blockDim.x) {
        g_outnorm[n] = rsqrtf(fmaxf((float)g_degout[n], 1.0f));
        g_innorm[n]  = rsqrtf(fmaxf((float)g_degin[n], 1.0f));
    }
}

__global__ void k_scan() {
    __shared__ int s[1024];
    const int CH = 49;
    int tid = threadIdx.x;
    int base = tid * CH;
    int tot = 0;
    for (int i = 0; i < CH; i++) {
        int idx = base + i;
        if (idx < N_NODES) tot += g_degin[idx];
    }
    s[tid] = tot;
    __syncthreads();
    for (int off = 1; off < 1024; off <<= 1) {
        int v = (tid >= off) ? s[tid - off] : 0;
        __syncthreads();
        s[tid] += v;
        __syncthreads();
    }
    int run = (tid > 0) ? s[tid - 1] : 0;
    for (int i = 0; i < CH; i++) {
        int idx = base + i;
        if (idx < N_NODES) {
            g_rowptr[idx] = run;
            g_cursor[idx] = run;
            run += g_degin[idx];
        } else if (idx == N_NODES) {
            g_rowptr[idx] = run;
        }
    }
}

__global__ void k_csr(const int* __restrict__ src, const int* __restrict__ dst) {
    for (int e = blockIdx.x * blockDim.x + threadIdx.x; e < E_EDGES;
         e += gridDim.x * blockDim.x) {
        int pos = atomicAdd(&g_cursor[dst[e]], 1);
        g_csrsrc[pos] = src[e];
    }
}

// ---------------- batched layer-1 GEMM via tf32 mma (R12 version) -------------
#define GEMM_TILES (782 * T_STEPS)
__global__ void __launch_bounds__(256) k_gemm_b(const float* __restrict__ X) {
    __shared__ __align__(16) float xs[64 * 68];
    __shared__ __align__(16) float sW[64 * 68];
    __shared__ float snorm[64];
    int tid = threadIdx.x, w = tid >> 5, lane = tid & 31;
    int gid = lane >> 2, tig = lane & 3;

    for (int idx = tid; idx < 4096; idx += 256) {
        int out = idx >> 6, k = idx & 63;
        sW[out * 68 + (k >> 3) * 8 + kperm(k & 7)] = __uint_as_float(g_W0g[idx]);
    }
    __syncthreads();
    float2 bw[8];
    {
        int col = w * 8 + gid;
#pragma unroll
        for (int ks = 0; ks < 8; ks++)
            bw[ks] = *(float2*)&sW[col * 68 + ks * 8 + tig * 2];
    }
    float bv0 = g_bvec0[w * 8 + tig * 2];
    float bv1 = g_bvec0[w * 8 + tig * 2 + 1];

    for (int tile = blockIdx.x; tile < GEMM_TILES; tile += gridDim.x) {
        int t = tile / 782;
        int n0 = (tile % 782) * 64;
#pragma unroll
        for (int i = 0; i < 4; i++) {
            int idx = tid + i * 256;
            int r = idx >> 4, q = idx & 15;
            int n = n0 + r;
            float4 v = make_float4(0, 0, 0, 0);
            if (n < N_NODES)
                v = *(const float4*)&X[((size_t)n * T_STEPS + t) * 64 + q * 4];
            int base = r * 68 + (q >> 1) * 8 + (q & 1);
            xs[base + 0] = __uint_as_float(tf32r(v.x));
            xs[base + 2] = __uint_as_float(tf32r(v.y));
            xs[base + 4] = __uint_as_float(tf32r(v.z));
            xs[base + 6] = __uint_as_float(tf32r(v.w));
        }
        if (tid < 64) {
            int n = n0 + tid;
            snorm[tid] = (n < N_NODES) ? g_outnorm[n] : 0.0f;
        }
        __syncthreads();

        float acc[4][4];
#pragma unroll
        for (int mt = 0; mt < 4; mt++)
#pragma unroll
            for (int c = 0; c < 4; c++) acc[mt][c] = 0.0f;

#pragma unroll
        for (int ks = 0; ks < 8; ks++) {
            float2 af0[4], af1[4];
#pragma unroll
            for (int mt = 0; mt < 4; mt++) {
                af0[mt] = *(float2*)&xs[(mt * 16 + gid) * 68 + ks * 8 + tig * 2];
                af1[mt] = *(float2*)&xs[(mt * 16 + gid + 8) * 68 + ks * 8 + tig * 2];
            }
#pragma unroll
            for (int mt = 0; mt < 4; mt++)
                asm volatile(
                    "mma.sync.aligned.m16n8k8.row.col.f32.tf32.tf32.f32 "
                    "{%0,%1,%2,%3}, {%4,%5,%6,%7}, {%8,%9}, {%0,%1,%2,%3};"
                    : "+f"(acc[mt][0]), "+f"(acc[mt][1]),
                      "+f"(acc[mt][2]), "+f"(acc[mt][3])
                    : "r"(__float_as_uint(af0[mt].x)), "r"(__float_as_uint(af1[mt].x)),
                      "r"(__float_as_uint(af0[mt].y)), "r"(__float_as_uint(af1[mt].y)),
                      "r"(__float_as_uint(bw[ks].x)), "r"(__float_as_uint(bw[ks].y)));
        }

        unsigned tb = (unsigned)t * N_NODES;
#pragma unroll
        for (int mt = 0; mt < 4; mt++) {
            int r0 = mt * 16 + gid;
            int n1 = n0 + r0, n2 = n1 + 8;
            if (n1 < N_NODES) {
                float sc = snorm[r0];
                g_M1[(tb + n1) * 32 + w * 4 + tig] =
                    bf2pack(sc * (acc[mt][0] + bv0), sc * (acc[mt][1] + bv1));
            }
            if (n2 < N_NODES) {
                float sc = snorm[r0 + 8];
                g_M1[(tb + n2) * 32 + w * 4 + tig] =
                    bf2pack(sc * (acc[mt][2] + bv0), sc * (acc[mt][3] + bv1));
            }
        }
        __syncthreads();
    }
}

// ---------------- gather layer1 (R12 t-major queue) ---------------------------
#define GTPT ((N_NODES + 127) / 128)        // 391
#define GTILES (GTPT * T_STEPS)             // 9384
__global__ void __launch_bounds__(256, 8) k_gatherA(const float* __restrict__ W1,
                                                    const float* __restrict__ b0) {
    __shared__ __align__(16) ull sW1p[64 * 32];
    __shared__ float sY[8][64];
    __shared__ int stile;
    int tid = threadIdx.x;
    int lane = tid & 31, w = tid >> 5;
    for (int idx = tid; idx < 2048; idx += 256) {
        int k = idx >> 5, c = idx & 31;
        float2 ww = *(const float2*)&W1[k * 64 + c * 2];
        sW1p[idx] = pack2f(ww.x, ww.y);
    }
    float bb0 = b0[2 * lane], bb1 = b0[2 * lane + 1];
    __syncthreads();

    for (;;) {
        if (tid == 0) stile = atomicAdd(&g_wqA, 1);
        __syncthreads();
        int tile = stile;
        if (tile >= GTILES) break;
        int t = tile / GTPT;
        int c0 = (tile % GTPT) * 128 + w * 16;
        unsigned base = (unsigned)t * N_NODES;

#pragma unroll 1
        for (int it = 0; it < 16; it++) {
            int v = c0 + it;
            if (v >= N_NODES) break;
            int s = g_rowptr[v], e = g_rowptr[v + 1];
            float a0 = 0.0f, a1 = 0.0f;
            int i = s;
            for (; i + 4 <= e; i += 4) {
                int u0 = g_csrsrc[i + 0];
                int u1 = g_csrsrc[i + 1];
                int u2 = g_csrsrc[i + 2];
                int u3 = g_csrsrc[i + 3];
                float2 m0 = bf2unpack(g_M1[(base + u0) * 32 + lane]);
                float2 m1 = bf2unpack(g_M1[(base + u1) * 32 + lane]);
                float2 m2 = bf2unpack(g_M1[(base + u2) * 32 + lane]);
                float2 m3 = bf2unpack(g_M1[(base + u3) * 32 + lane]);
                a0 += (m0.x + m1.x) + (m2.x + m3.x);
                a1 += (m0.y + m1.y) + (m2.y + m3.y);
            }
            for (; i < e; i++) {
                int u = g_csrsrc[i];
                float2 m = bf2unpack(g_M1[(base + u) * 32 + lane]);
                a0 += m.x; a1 += m.y;
            }
            float inn = g_innorm[v];
            sY[w][2 * lane]     = gelu_f(a0 * inn + bb0);
            sY[w][2 * lane + 1] = gelu_f(a1 * inn + bb1);
            __syncwarp();
            ull acc = 0ull;
#pragma unroll 8
            for (int k = 0; k < 64; k++)
                acc = ffma2(dup2f(sY[w][k]), sW1p[k * 32 + lane], acc);
            float2 p = unpack2(acc);
            float sc = g_outnorm[v];
            g_M2[(base + v) * 32 + lane] = bf2pack(sc * p.x, sc * p.y);
            __syncwarp();
        }
        __syncthreads();
    }
}

// ---------------- gather layer2 + mean (R12 t-major queue) --------------------
__global__ void __launch_bounds__(256, 8) k_gatherB(const float* __restrict__ b1,
                                                    float* __restrict__ out) {
    __shared__ float red[64];
    __shared__ int stile;
    int tid = threadIdx.x;
    int lane = tid & 31, w = tid >> 5;
    float bb0 = b1[2 * lane], bb1 = b1[2 * lane + 1];

    for (;;) {
        if (tid == 0) stile = atomicAdd(&g_wqB, 1);
        __syncthreads();
        int tile = stile;
        if (tile >= GTILES) break;
        int t = tile / GTPT;
        int c0 = (tile % GTPT) * 128 + w * 16;
        unsigned base = (unsigned)t * N_NODES;
        float acc0t = 0.0f, acc1t = 0.0f;

#pragma unroll 1
        for (int it = 0; it < 16; it++) {
            int v = c0 + it;
            if (v >= N_NODES) break;
            int s = g_rowptr[v], e = g_rowptr[v + 1];
            float a0 = 0.0f, a1 = 0.0f;
            int i = s;
            for (; i + 4 <= e; i += 4) {
                int u0 = g_csrsrc[i + 0];
                int u1 = g_csrsrc[i + 1];
                int u2 = g_csrsrc[i + 2];
                int u3 = g_csrsrc[i + 3];
                float2 m0 = bf2unpack(g_M2[(base + u0) * 32 + lane]);
                float2 m1 = bf2unpack(g_M2[(base + u1) * 32 + lane]);
                float2 m2 = bf2unpack(g_M2[(base + u2) * 32 + lane]);
                float2 m3 = bf2unpack(g_M2[(base + u3) * 32 + lane]);
                a0 += (m0.x + m1.x) + (m2.x + m3.x);
                a1 += (m0.y + m1.y) + (m2.y + m3.y);
            }
            for (; i < e; i++) {
                int u = g_csrsrc[i];
                float2 m = bf2unpack(g_M2[(base + u) * 32 + lane]);
                a0 += m.x; a1 += m.y;
            }
            float inn = g_innorm[v];
            acc0t += gelu_f(a0 * inn + bb0);
            acc1t += gelu_f(a1 * inn + bb1);
        }
        if (tid < 64) red[tid] = 0.0f;
        __syncthreads();
        atomicAdd(&red[2 * lane + 0], acc0t);
        atomicAdd(&red[2 * lane + 1], acc1t);
        __syncthreads();
        if (tid < 64)
            atomicAdd(&out[t * 64 + tid], red[tid] * (1.0f / (float)N_NODES));
        __syncthreads();
    }
}

// ---------------- tensorized persistent LSTM: 16 warps, M-split ---------------
// Warp (ws, wm): ws = M-half (rows ws*32..ws*32+31), wm = hidden-unit group
// (units wm*8..wm*8+7, all 4 gates). Same smem + numerics as R10/R12; 2x warps
// per SMSP for latency hiding (issue 42% -> target ~70%).
#define LSTM_THREADS 512
#define LSTM_SMEM_BYTES (48128 * 4)
__global__ void __launch_bounds__(LSTM_THREADS, 1) k_lstm_fused(
    const float* __restrict__ h_all, float* __restrict__ out_ht) {
    extern __shared__ float sm[];
    float* xs  = sm;              // [64][68]
    float* hhi = sm + 4352;
    float* hlo = sm + 8704;
    float* sWi = sm + 13056;      // [256][68] perm layout
    float* sWh = sm + 30464;
    __shared__ int sgrp;

    int tid = threadIdx.x, w = tid >> 5, lane = tid & 31;
    int gid = lane >> 2, tig = lane & 3;
    int wm = w & 7, ws = w >> 3;
    int rbase = ws * 32;

    for (int idx = tid; idx < 16384; idx += LSTM_THREADS) {
        int col = idx >> 6, k = idx & 63;
        int slot = col * 68 + (k >> 3) * 8 + kperm(k & 7);
        sWi[slot] = __uint_as_float(g_Wg[idx]);
        sWh[slot] = __uint_as_float(g_Whg[idx]);
    }
    int u0 = wm * 8 + tig * 2;
    float bi0 = g_gbias[u0],       bi1 = g_gbias[u0 + 1];
    float bf0 = g_gbias[64 + u0],  bf1 = g_gbias[64 + u0 + 1];
    float bg0 = g_gbias[128 + u0], bg1 = g_gbias[128 + u0 + 1];
    float bo0 = g_gbias[192 + u0], bo1 = g_gbias[192 + u0 + 1];
    int p0 = ((2 * tig) & 3) * 2 + (tig >> 1);
    int p1 = ((2 * tig + 1) & 3) * 2 + (tig >> 1);
    __syncthreads();

    const int NGROUPS = (N_NODES + 63) / 64;   // 782
    const float inv = 1.0f / (float)T_STEPS;

    for (;;) {
        if (tid == 0) sgrp = atomicAdd(&g_wq, 1);
        __syncthreads();
        int grp = sgrp;
        if (grp >= NGROUPS) break;
        int n0 = grp * 64;

        float cst[8], hs[8];
#pragma unroll
        for (int i = 0; i < 8; i++) { cst[i] = 0.0f; hs[i] = 0.0f; }
        for (int idx = tid; idx < 4352; idx += LSTM_THREADS) {
            hhi[idx] = 0.0f; hlo[idx] = 0.0f;
        }
        __syncthreads();

        for (int t = 0; t < T_STEPS; t++) {
            // ---- stage x tile (tf32, perm) ----
#pragma unroll
            for (int i = 0; i < 2; i++) {
                int idx = tid + i * LSTM_THREADS;
                int r = idx >> 4, q = idx & 15;
                int n = n0 + r;
                float4 v = make_float4(0, 0, 0, 0);
                if (n < N_NODES)
                    v = *(const float4*)&h_all[((size_t)n * T_STEPS + t) * 64 + q * 4];
                int base = r * 68 + (q >> 1) * 8 + (q & 1);
                xs[base + 0] = __uint_as_float(tf32r(v.x));
                xs[base + 2] = __uint_as_float(tf32r(v.y));
                xs[base + 4] = __uint_as_float(tf32r(v.z));
                xs[base + 6] = __uint_as_float(tf32r(v.w));
            }
            __syncthreads();

            // ---- tensor phase (this warp's 32 rows x 32 gate-cols) ----
            float acc[2][4][4];   // [mt][gate][4]
#pragma unroll
            for (int mt = 0; mt < 2; mt++)
#pragma unroll
                for (int g = 0; g < 4; g++)
#pragma unroll
                    for (int c = 0; c < 4; c++) acc[mt][g][c] = 0.0f;

#pragma unroll
            for (int pass = 0; pass < 3; pass++) {
                const float* A = (pass == 0) ? xs : (pass == 1) ? hhi : hlo;
                const float* W = (pass == 0) ? sWi : sWh;
#pragma unroll
                for (int ks = 0; ks < 8; ks++) {
                    float2 af0[2], af1[2];
#pragma unroll
                    for (int mt = 0; mt < 2; mt++) {
                        int r = rbase + mt * 16 + gid;
                        af0[mt] = *(float2*)&A[r * 68 + ks * 8 + tig * 2];
                        af1[mt] = *(float2*)&A[(r + 8) * 68 + ks * 8 + tig * 2];
                    }
#pragma unroll
                    for (int g = 0; g < 4; g++) {
                        float2 bwv = *(float2*)&W[(g * 64 + wm * 8 + gid) * 68 + ks * 8 + tig * 2];
#pragma unroll
                        for (int mt = 0; mt < 2; mt++)
                            asm volatile(
                                "mma.sync.aligned.m16n8k8.row.col.f32.tf32.tf32.f32 "
                                "{%0,%1,%2,%3}, {%4,%5,%6,%7}, {%8,%9}, {%0,%1,%2,%3};"
                                : "+f"(acc[mt][g][0]), "+f"(acc[mt][g][1]),
                                  "+f"(acc[mt][g][2]), "+f"(acc[mt][g][3])
                                : "r"(__float_as_uint(af0[mt].x)), "r"(__float_as_uint(af1[mt].x)),
                                  "r"(__float_as_uint(af0[mt].y)), "r"(__float_as_uint(af1[mt].y)),
                                  "r"(__float_as_uint(bwv.x)), "r"(__float_as_uint(bwv.y)));
                    }
                }
            }

            // ---- in-register gate math ----
#pragma unroll
            for (int mt = 0; mt < 2; mt++) {
#pragma unroll
                for (int j = 0; j < 4; j++) {
                    float gi = acc[mt][0][j] + ((j & 1) ? bi1 : bi0);
                    float gf = acc[mt][1][j] + ((j & 1) ? bf1 : bf0);
                    float gg = acc[mt][2][j] + ((j & 1) ? bg1 : bg0);
                    float go = acc[mt][3][j] + ((j & 1) ? bo1 : bo0);
                    int ci = mt * 4 + j;
                    float cn = sigf(gf) * cst[ci] + sigf(gi) * tanhfast(gg);
                    float hv = sigf(go) * tanhfast(cn);
                    cst[ci] = cn;
                    hs[ci] += hv;
                    int row = rbase + mt * 16 + gid + ((j >> 1) ? 8 : 0);
                    float hi = __uint_as_float(tf32r(hv));
                    int slot = row * 68 + wm * 8 + ((j & 1) ? p1 : p0);
                    hhi[slot] = hi;
                    hlo[slot] = __uint_as_float(tf32r(hv - hi));
                }
            }
            __syncthreads();
        }

        // ---- readout ----
#pragma unroll
        for (int mt = 0; mt < 2; mt++) {
#pragma unroll
            for (int jr = 0; jr < 2; jr++) {
                int row = rbase + mt * 16 + gid + jr * 8;
                int n = n0 + row;
                if (n < N_NODES)
                    *(float2*)&out_ht[n * 64 + u0] =
                        make_float2(hs[mt * 4 + jr * 2] * inv, hs[mt * 4 + jr * 2 + 1] * inv);
            }
        }
        __syncthreads();
    }
}

__global__ void k_join_anchor() {}

// ---------------- launch ------------------------------------------------------
extern "C" void kernel_launch(void* const* d_in, const int* in_sizes, int n_in,
                              void* d_out, int out_size) {
    const float* h     = (const float*)d_in[0];
    const int*   src   = (const int*)d_in[1];
    const int*   dst   = (const int*)d_in[2];
    const float* gamma = (const float*)d_in[3];
    const float* beta  = (const float*)d_in[4];
    const float* W0    = (const float*)d_in[5];
    const float* b0    = (const float*)d_in[6];
    const float* W1    = (const float*)d_in[7];
    const float* b1    = (const float*)d_in[8];
    const float* Wih   = (const float*)d_in[9];
    const float* Whh   = (const float*)d_in[10];
    const float* bih   = (const float*)d_in[11];
    const float* bhh   = (const float*)d_in[12];
    float* out = (float*)d_out;
    (void)in_sizes; (void)n_in;

    // one-time resource setup OUTSIDE graph capture
    static cudaStream_t s1 = 0;
    static cudaEvent_t eFork = 0, eNorm = 0, eGemm = 0, eJoin = 0;
    static int multi = -1;
    if (multi < 0) {
        bool ok = (cudaStreamCreateWithFlags(&s1, cudaStreamNonBlocking) == cudaSuccess);
        if (ok) ok = (cudaEventCreateWithFlags(&eFork, cudaEventDisableTiming) == cudaSuccess);
        if (ok) ok = (cudaEventCreateWithFlags(&eNorm, cudaEventDisableTiming) == cudaSuccess);
        if (ok) ok = (cudaEventCreateWithFlags(&eGemm, cudaEventDisableTiming) == cudaSuccess);
        if (ok) ok = (cudaEventCreateWithFlags(&eJoin, cudaEventDisableTiming) == cudaSuccess);
        cudaFuncSetAttribute(k_lstm_fused, cudaFuncAttributeMaxDynamicSharedMemorySize,
                             LSTM_SMEM_BYTES);
        multi = ok ? 1 : 0;
    }
    cudaStream_t sg = multi ? s1 : (cudaStream_t)0;

    // stream 0: init -> fork -> BN -> prepall -> (wait norm) gemm -> LSTM
    k_init<<<512, 256>>>(out, out_size);
    if (multi) {
        cudaEventRecord(eFork, 0);
        cudaStreamWaitEvent(sg, eFork, 0);
    }
    k_bnstats<<<1184, 256>>>((const float4*)h);
    k_prepall<<<33, 256>>>(gamma, beta, W0, Wih, Whh, bih, bhh);

    // sg: graph structure (concurrent with BN/prep when multi)
    k_deg<<<800, 256, 0, sg>>>(src, dst);
    k_norm<<<128, 256, 0, sg>>>();
    if (multi) {
        cudaEventRecord(eNorm, sg);
        cudaStreamWaitEvent(0, eNorm, 0);   // gemm needs g_outnorm
    }
    k_scan<<<1, 1024, 0, sg>>>();
    k_csr<<<800, 256, 0, sg>>>(src, dst);

    // stream 0: gemm (full chip), then persistent LSTM
    k_gemm_b<<<592, 256, 0, 0>>>(h);
    if (multi) {
        cudaEventRecord(eGemm, 0);
        cudaStreamWaitEvent(sg, eGemm, 0);  // gathers need M1
    }
    k_lstm_fused<<<148, LSTM_THREADS, LSTM_SMEM_BYTES>>>(h, out + T_STEPS * 64);

    // sg: gathers
    k_gatherA<<<1184, 256, 0, sg>>>(W1, b0);
    k_gatherB<<<1184, 256, 0, sg>>>(b1, out);

    if (multi) {
        cudaEventRecord(eJoin, sg);
        cudaStreamWaitEvent(0, eJoin, 0);
        k_join_anchor<<<1, 1, 0, 0>>>();
    }
}

// round 16
// speedup vs baseline: 1.0485x; 1.0485x over previous
#include <cuda_runtime.h>
#include <cuda_bf16.h>
#include <math.h>
#include <stdint.h>

#define N_NODES 50000
#define T_STEPS 24
#define E_EDGES 800000
#define NT_ROWS (N_NODES * T_STEPS)

typedef unsigned long long ull;

// ---------------- packed helpers ---------------------------------------------
__device__ __forceinline__ ull ffma2(ull a, ull b, ull c) {
    ull d;
    asm("fma.rn.f32x2 %0, %1, %2, %3;" : "=l"(d) : "l"(a), "l"(b), "l"(c));
    return d;
}
__device__ __forceinline__ ull dup2f(float x) {
    ull r; asm("mov.b64 %0, {%1, %1};" : "=l"(r) : "f"(x)); return r;
}
__device__ __forceinline__ ull pack2f(float x, float y) {
    ull r; asm("mov.b64 %0, {%1, %2};" : "=l"(r) : "f"(x), "f"(y)); return r;
}
__device__ __forceinline__ float2 unpack2(ull v) {
    float2 r; asm("mov.b64 {%0, %1}, %2;" : "=f"(r.x), "=f"(r.y) : "l"(v)); return r;
}
__device__ __forceinline__ unsigned bf2pack(float x, float y) {
    __nv_bfloat162 b = __float22bfloat162_rn(make_float2(x, y));
    return *(unsigned*)&b;
}
__device__ __forceinline__ float2 bf2unpack(unsigned u) {
    __nv_bfloat162 b = *(__nv_bfloat162*)&u;
    return __bfloat1622float2(b);
}
__device__ __forceinline__ unsigned tf32r(float f) {
    unsigned u; asm("cvt.rna.tf32.f32 %0, %1;" : "=r"(u) : "f"(f)); return u;
}
// fast sigmoid/tanh: ex2.approx + rcp.approx (rel err ~1e-6)
__device__ __forceinline__ float sigf(float x) {
    float e, r;
    asm("ex2.approx.f32 %0, %1;" : "=f"(e) : "f"(-1.442695041f * x));
    asm("rcp.approx.f32 %0, %1;" : "=f"(r) : "f"(1.0f + e));
    return r;
}
__device__ __forceinline__ float tanhfast(float x) {
    return fmaf(2.0f, sigf(2.0f * x), -1.0f);
}

// ---------------- scratch (device globals) ----------------------------------
__device__ float g_sum[64];
__device__ float g_sumsq[64];
__device__ float g_bvec0[64];
__device__ float g_gbias[256];
__device__ unsigned g_Wg[256 * 64];     // tf32 bits of a*Wih, [g][k]
__device__ unsigned g_Whg[256 * 64];    // tf32 bits of Whh,   [g][k]
__device__ unsigned g_W0g[64 * 64];     // tf32 bits of a*W0,  [out][k]
__device__ float g_outnorm[N_NODES];
__device__ float g_innorm[N_NODES];
__device__ int   g_degout[N_NODES];
__device__ int   g_degin[N_NODES];
__device__ int   g_rowptr[N_NODES + 1];
__device__ int   g_cursor[N_NODES];
__device__ int   g_csrsrc[E_EDGES];
__device__ unsigned g_M1[T_STEPS * N_NODES * 32];
__device__ unsigned g_M2[T_STEPS * N_NODES * 32];
__device__ int   g_wq;
__device__ int   g_wqA;
__device__ int   g_wqB;

__device__ __forceinline__ float gelu_f(float x) {
    return 0.5f * x * (1.0f + erff(x * 0.70710678118654752440f));
}

// permuted k-slot within an 8-k block so (k, k+4) pairs are adjacent
__device__ __forceinline__ int kperm(int k) {   // k in 0..7
    return (k & 3) * 2 + (k >> 2);
}

// ---------------- init -------------------------------------------------------
__global__ void k_init(float* out, int out_n) {
    int i = blockIdx.x * blockDim.x + threadIdx.x;
    int stride = gridDim.x * blockDim.x;
    for (int j = i; j < out_n; j += stride) out[j] = 0.0f;
    for (int j = i; j < N_NODES; j += stride) { g_degout[j] = 0; g_degin[j] = 0; }
    if (i < 64) { g_sum[i] = 0.0f; g_sumsq[i] = 0.0f; }
    if (i == 0) { g_wq = 0; g_wqA = 0; g_wqB = 0; }
}

// ---------------- BN stats ---------------------------------------------------
__global__ void k_bnstats(const float4* __restrict__ h4) {
    __shared__ float ss[64], sq[64];
    int tid = threadIdx.x;
    if (tid < 64) { ss[tid] = 0.0f; sq[tid] = 0.0f; }
    __syncthreads();
    const int total4 = NT_ROWS * 16;
    float4 s = make_float4(0, 0, 0, 0);
    float4 q = make_float4(0, 0, 0, 0);
    for (int i = blockIdx.x * blockDim.x + tid; i < total4; i += gridDim.x * blockDim.x) {
        float4 v = h4[i];
        s.x += v.x; s.y += v.y; s.z += v.z; s.w += v.w;
        q.x += v.x * v.x; q.y += v.y * v.y; q.z += v.z * v.z; q.w += v.w * v.w;
    }
    int c = (tid & 15) * 4;
    atomicAdd(&ss[c + 0], s.x); atomicAdd(&ss[c + 1], s.y);
    atomicAdd(&ss[c + 2], s.z); atomicAdd(&ss[c + 3], s.w);
    atomicAdd(&sq[c + 0], q.x); atomicAdd(&sq[c + 1], q.y);
    atomicAdd(&sq[c + 2], q.z); atomicAdd(&sq[c + 3], q.w);
    __syncthreads();
    if (tid < 64) {
        atomicAdd(&g_sum[tid], ss[tid]);
        atomicAdd(&g_sumsq[tid], sq[tid]);
    }
}

// ---------------- merged prep ------------------------------------------------
__global__ void k_prepall(const float* __restrict__ gamma, const float* __restrict__ beta,
                          const float* __restrict__ W0,   const float* __restrict__ Wih,
                          const float* __restrict__ Whh,  const float* __restrict__ bih,
                          const float* __restrict__ bhh) {
    __shared__ float sa[64], sb[64];
    int tid = threadIdx.x;
    if (tid < 64) {
        float mu  = g_sum[tid]   * (1.0f / (float)NT_ROWS);
        float var = g_sumsq[tid] * (1.0f / (float)NT_ROWS) - mu * mu;
        float a = gamma[tid] * rsqrtf(var + 1e-5f);
        sa[tid] = a;
        sb[tid] = beta[tid] - mu * a;
    }
    __syncthreads();
    int b = blockIdx.x;
    if (b == 32) {
        for (int idx = tid; idx < 4096; idx += 256) {
            int out = idx >> 6, k = idx & 63;
            g_W0g[idx] = tf32r(sa[k] * W0[k * 64 + out]);
        }
        if (tid < 64) {
            float acc = 0.0f;
            for (int k = 0; k < 64; k++) acc += sb[k] * W0[k * 64 + tid];
            g_bvec0[tid] = acc;
        }
        {   // gate bias
            float acc = bih[tid] + bhh[tid];
            for (int k = 0; k < 64; k++) acc += sb[k] * Wih[tid * 64 + k];
            g_gbias[tid] = acc;
        }
    } else {
        for (int i = tid; i < 512; i += 256) {
            int idx = b * 512 + i;
            int g = idx >> 6, k = idx & 63;
            g_Wg[idx]  = tf32r(sa[k] * Wih[g * 64 + k]);
            g_Whg[idx] = tf32r(Whh[g * 64 + k]);
        }
    }
}

// ---------------- degrees / norms / CSR --------------------------------------
__global__ void k_deg(const int* __restrict__ src, const int* __restrict__ dst) {
    for (int e = blockIdx.x * blockDim.x + threadIdx.x; e < E_EDGES;
         e += gridDim.x * blockDim.x) {
        atomicAdd(&g_degout[src[e]], 1);
        atomicAdd(&g_degin[dst[e]], 1);
    }
}

__global__ void k_norm() {
    for (int n = blockIdx.x * blockDim.x + threadIdx.x; n < N_NODES;
         n += gridDim.x * blockDim.x) {
        g_outnorm[n] = rsqrtf(fmaxf((float)g_degout[n], 1.0f));
        g_innorm[n]  = rsqrtf(fmaxf((float)g_degin[n], 1.0f));
    }
}

__global__ void k_scan() {
    __shared__ int s[1024];
    const int CH = 49;
    int tid = threadIdx.x;
    int base = tid * CH;
    int tot = 0;
    for (int i = 0; i < CH; i++) {
        int idx = base + i;
        if (idx < N_NODES) tot += g_degin[idx];
    }
    s[tid] = tot;
    __syncthreads();
    for (int off = 1; off < 1024; off <<= 1) {
        int v = (tid >= off) ? s[tid - off] : 0;
        __syncthreads();
        s[tid] += v;
        __syncthreads();
    }
    int run = (tid > 0) ? s[tid - 1] : 0;
    for (int i = 0; i < CH; i++) {
        int idx = base + i;
        if (idx < N_NODES) {
            g_rowptr[idx] = run;
            g_cursor[idx] = run;
            run += g_degin[idx];
        } else if (idx == N_NODES) {
            g_rowptr[idx] = run;
        }
    }
}

__global__ void k_csr(const int* __restrict__ src, const int* __restrict__ dst) {
    for (int e = blockIdx.x * blockDim.x + threadIdx.x; e < E_EDGES;
         e += gridDim.x * blockDim.x) {
        int pos = atomicAdd(&g_cursor[dst[e]], 1);
        g_csrsrc[pos] = src[e];
    }
}

// ---------------- batched layer-1 GEMM via tf32 mma (R12 version) -------------
#define GEMM_TILES (782 * T_STEPS)
__global__ void __launch_bounds__(256) k_gemm_b(const float* __restrict__ X) {
    __shared__ __align__(16) float xs[64 * 68];
    __shared__ __align__(16) float sW[64 * 68];
    __shared__ float snorm[64];
    int tid = threadIdx.x, w = tid >> 5, lane = tid & 31;
    int gid = lane >> 2, tig = lane & 3;

    for (int idx = tid; idx < 4096; idx += 256) {
        int out = idx >> 6, k = idx & 63;
        sW[out * 68 + (k >> 3) * 8 + kperm(k & 7)] = __uint_as_float(g_W0g[idx]);
    }
    __syncthreads();
    float2 bw[8];
    {
        int col = w * 8 + gid;
#pragma unroll
        for (int ks = 0; ks < 8; ks++)
            bw[ks] = *(float2*)&sW[col * 68 + ks * 8 + tig * 2];
    }
    float bv0 = g_bvec0[w * 8 + tig * 2];
    float bv1 = g_bvec0[w * 8 + tig * 2 + 1];

    for (int tile = blockIdx.x; tile < GEMM_TILES; tile += gridDim.x) {
        int t = tile / 782;
        int n0 = (tile % 782) * 64;
#pragma unroll
        for (int i = 0; i < 4; i++) {
            int idx = tid + i * 256;
            int r = idx >> 4, q = idx & 15;
            int n = n0 + r;
            float4 v = make_float4(0, 0, 0, 0);
            if (n < N_NODES)
                v = *(const float4*)&X[((size_t)n * T_STEPS + t) * 64 + q * 4];
            int base = r * 68 + (q >> 1) * 8 + (q & 1);
            xs[base + 0] = __uint_as_float(tf32r(v.x));
            xs[base + 2] = __uint_as_float(tf32r(v.y));
            xs[base + 4] = __uint_as_float(tf32r(v.z));
            xs[base + 6] = __uint_as_float(tf32r(v.w));
        }
        if (tid < 64) {
            int n = n0 + tid;
            snorm[tid] = (n < N_NODES) ? g_outnorm[n] : 0.0f;
        }
        __syncthreads();

        float acc[4][4];
#pragma unroll
        for (int mt = 0; mt < 4; mt++)
#pragma unroll
            for (int c = 0; c < 4; c++) acc[mt][c] = 0.0f;

#pragma unroll
        for (int ks = 0; ks < 8; ks++) {
            float2 af0[4], af1[4];
#pragma unroll
            for (int mt = 0; mt < 4; mt++) {
                af0[mt] = *(float2*)&xs[(mt * 16 + gid) * 68 + ks * 8 + tig * 2];
                af1[mt] = *(float2*)&xs[(mt * 16 + gid + 8) * 68 + ks * 8 + tig * 2];
            }
#pragma unroll
            for (int mt = 0; mt < 4; mt++)
                asm volatile(
                    "mma.sync.aligned.m16n8k8.row.col.f32.tf32.tf32.f32 "
                    "{%0,%1,%2,%3}, {%4,%5,%6,%7}, {%8,%9}, {%0,%1,%2,%3};"
                    : "+f"(acc[mt][0]), "+f"(acc[mt][1]),
                      "+f"(acc[mt][2]), "+f"(acc[mt][3])
                    : "r"(__float_as_uint(af0[mt].x)), "r"(__float_as_uint(af1[mt].x)),
                      "r"(__float_as_uint(af0[mt].y)), "r"(__float_as_uint(af1[mt].y)),
                      "r"(__float_as_uint(bw[ks].x)), "r"(__float_as_uint(bw[ks].y)));
        }

        unsigned tb = (unsigned)t * N_NODES;
#pragma unroll
        for (int mt = 0; mt < 4; mt++) {
            int r0 = mt * 16 + gid;
            int n1 = n0 + r0, n2 = n1 + 8;
            if (n1 < N_NODES) {
                float sc = snorm[r0];
                g_M1[(tb + n1) * 32 + w * 4 + tig] =
                    bf2pack(sc * (acc[mt][0] + bv0), sc * (acc[mt][1] + bv1));
            }
            if (n2 < N_NODES) {
                float sc = snorm[r0 + 8];
                g_M1[(tb + n2) * 32 + w * 4 + tig] =
                    bf2pack(sc * (acc[mt][2] + bv0), sc * (acc[mt][3] + bv1));
            }
        }
        __syncthreads();
    }
}

// ---------------- gather layer1 (t-major queue; 8-wide MLP) -------------------
#define GTPT ((N_NODES + 127) / 128)        // 391
#define GTILES (GTPT * T_STEPS)             // 9384
__global__ void __launch_bounds__(256, 6) k_gatherA(const float* __restrict__ W1,
                                                    const float* __restrict__ b0) {
    __shared__ __align__(16) ull sW1p[64 * 32];
    __shared__ float sY[8][64];
    __shared__ int stile;
    int tid = threadIdx.x;
    int lane = tid & 31, w = tid >> 5;
    for (int idx = tid; idx < 2048; idx += 256) {
        int k = idx >> 5, c = idx & 31;
        float2 ww = *(const float2*)&W1[k * 64 + c * 2];
        sW1p[idx] = pack2f(ww.x, ww.y);
    }
    float bb0 = b0[2 * lane], bb1 = b0[2 * lane + 1];
    __syncthreads();

    for (;;) {
        if (tid == 0) stile = atomicAdd(&g_wqA, 1);
        __syncthreads();
        int tile = stile;
        if (tile >= GTILES) break;
        int t = tile / GTPT;
        int c0 = (tile % GTPT) * 128 + w * 16;
        unsigned base = (unsigned)t * N_NODES;

#pragma unroll 1
        for (int it = 0; it < 16; it++) {
            int v = c0 + it;
            if (v >= N_NODES) break;
            int s = g_rowptr[v], e = g_rowptr[v + 1];
            float a0 = 0.0f, a1 = 0.0f;
            int i = s;
            for (; i + 8 <= e; i += 8) {
                int u[8];
#pragma unroll
                for (int j = 0; j < 8; j++) u[j] = g_csrsrc[i + j];
                float2 m[8];
#pragma unroll
                for (int j = 0; j < 8; j++)
                    m[j] = bf2unpack(g_M1[(base + u[j]) * 32 + lane]);
                a0 += ((m[0].x + m[1].x) + (m[2].x + m[3].x))
                    + ((m[4].x + m[5].x) + (m[6].x + m[7].x));
                a1 += ((m[0].y + m[1].y) + (m[2].y + m[3].y))
                    + ((m[4].y + m[5].y) + (m[6].y + m[7].y));
            }
            for (; i + 4 <= e; i += 4) {
                int u0 = g_csrsrc[i + 0];
                int u1 = g_csrsrc[i + 1];
                int u2 = g_csrsrc[i + 2];
                int u3 = g_csrsrc[i + 3];
                float2 m0 = bf2unpack(g_M1[(base + u0) * 32 + lane]);
                float2 m1 = bf2unpack(g_M1[(base + u1) * 32 + lane]);
                float2 m2 = bf2unpack(g_M1[(base + u2) * 32 + lane]);
                float2 m3 = bf2unpack(g_M1[(base + u3) * 32 + lane]);
                a0 += (m0.x + m1.x) + (m2.x + m3.x);
                a1 += (m0.y + m1.y) + (m2.y + m3.y);
            }
            for (; i < e; i++) {
                int u = g_csrsrc[i];
                float2 m = bf2unpack(g_M1[(base + u) * 32 + lane]);
                a0 += m.x; a1 += m.y;
            }
            float inn = g_innorm[v];
            sY[w][2 * lane]     = gelu_f(a0 * inn + bb0);
            sY[w][2 * lane + 1] = gelu_f(a1 * inn + bb1);
            __syncwarp();
            ull acc = 0ull;
#pragma unroll 8
            for (int k = 0; k < 64; k++)
                acc = ffma2(dup2f(sY[w][k]), sW1p[k * 32 + lane], acc);
            float2 p = unpack2(acc);
            float sc = g_outnorm[v];
            g_M2[(base + v) * 32 + lane] = bf2pack(sc * p.x, sc * p.y);
            __syncwarp();
        }
        __syncthreads();
    }
}

// ---------------- gather layer2 + mean (t-major queue; 8-wide MLP) ------------
__global__ void __launch_bounds__(256, 6) k_gatherB(const float* __restrict__ b1,
                                                    float* __restrict__ out) {
    __shared__ float red[64];
    __shared__ int stile;
    int tid = threadIdx.x;
    int lane = tid & 31, w = tid >> 5;
    float bb0 = b1[2 * lane], bb1 = b1[2 * lane + 1];

    for (;;) {
        if (tid == 0) stile = atomicAdd(&g_wqB, 1);
        __syncthreads();
        int tile = stile;
        if (tile >= GTILES) break;
        int t = tile / GTPT;
        int c0 = (tile % GTPT) * 128 + w * 16;
        unsigned base = (unsigned)t * N_NODES;
        float acc0t = 0.0f, acc1t = 0.0f;

#pragma unroll 1
        for (int it = 0; it < 16; it++) {
            int v = c0 + it;
            if (v >= N_NODES) break;
            int s = g_rowptr[v], e = g_rowptr[v + 1];
            float a0 = 0.0f, a1 = 0.0f;
            int i = s;
            for (; i + 8 <= e; i += 8) {
                int u[8];
#pragma unroll
                for (int j = 0; j < 8; j++) u[j] = g_csrsrc[i + j];
                float2 m[8];
#pragma unroll
                for (int j = 0; j < 8; j++)
                    m[j] = bf2unpack(g_M2[(base + u[j]) * 32 + lane]);
                a0 += ((m[0].x + m[1].x) + (m[2].x + m[3].x))
                    + ((m[4].x + m[5].x) + (m[6].x + m[7].x));
                a1 += ((m[0].y + m[1].y) + (m[2].y + m[3].y))
                    + ((m[4].y + m[5].y) + (m[6].y + m[7].y));
            }
            for (; i + 4 <= e; i += 4) {
                int u0 = g_csrsrc[i + 0];
                int u1 = g_csrsrc[i + 1];
                int u2 = g_csrsrc[i + 2];
                int u3 = g_csrsrc[i + 3];
                float2 m0 = bf2unpack(g_M2[(base + u0) * 32 + lane]);
                float2 m1 = bf2unpack(g_M2[(base + u1) * 32 + lane]);
                float2 m2 = bf2unpack(g_M2[(base + u2) * 32 + lane]);
                float2 m3 = bf2unpack(g_M2[(base + u3) * 32 + lane]);
                a0 += (m0.x + m1.x) + (m2.x + m3.x);
                a1 += (m0.y + m1.y) + (m2.y + m3.y);
            }
            for (; i < e; i++) {
                int u = g_csrsrc[i];
                float2 m = bf2unpack(g_M2[(base + u) * 32 + lane]);
                a0 += m.x; a1 += m.y;
            }
            float inn = g_innorm[v];
            acc0t += gelu_f(a0 * inn + bb0);
            acc1t += gelu_f(a1 * inn + bb1);
        }
        if (tid < 64) red[tid] = 0.0f;
        __syncthreads();
        atomicAdd(&red[2 * lane + 0], acc0t);
        atomicAdd(&red[2 * lane + 1], acc1t);
        __syncthreads();
        if (tid < 64)
            atomicAdd(&out[t * 64 + tid], red[tid] * (1.0f / (float)N_NODES));
        __syncthreads();
    }
}

// ---------------- tensorized persistent LSTM (R14: 8 warps, in-reg gates) -----
#define LSTM_SMEM_BYTES (48128 * 4)
__global__ void __launch_bounds__(256, 1) k_lstm_fused(
    const float* __restrict__ h_all, float* __restrict__ out_ht) {
    extern __shared__ float sm[];
    float* xs  = sm;              // [64][68]
    float* hhi = sm + 4352;
    float* hlo = sm + 8704;
    float* sWi = sm + 13056;      // [256][68] perm layout
    float* sWh = sm + 30464;
    __shared__ int sgrp;

    int tid = threadIdx.x, w = tid >> 5, lane = tid & 31;
    int gid = lane >> 2, tig = lane & 3;

    for (int idx = tid; idx < 16384; idx += 256) {
        int col = idx >> 6, k = idx & 63;
        int slot = col * 68 + (k >> 3) * 8 + kperm(k & 7);
        sWi[slot] = __uint_as_float(g_Wg[idx]);
        sWh[slot] = __uint_as_float(g_Whg[idx]);
    }
    int u0 = w * 8 + tig * 2;
    float bi0 = g_gbias[u0],       bi1 = g_gbias[u0 + 1];
    float bf0 = g_gbias[64 + u0],  bf1 = g_gbias[64 + u0 + 1];
    float bg0 = g_gbias[128 + u0], bg1 = g_gbias[128 + u0 + 1];
    float bo0 = g_gbias[192 + u0], bo1 = g_gbias[192 + u0 + 1];
    int p0 = ((2 * tig) & 3) * 2 + (tig >> 1);
    int p1 = ((2 * tig + 1) & 3) * 2 + (tig >> 1);
    __syncthreads();

    const int NGROUPS = (N_NODES + 63) / 64;   // 782
    const float inv = 1.0f / (float)T_STEPS;

    for (;;) {
        if (tid == 0) sgrp = atomicAdd(&g_wq, 1);
        __syncthreads();
        int grp = sgrp;
        if (grp >= NGROUPS) break;
        int n0 = grp * 64;

        float cst[16], hs[16];
#pragma unroll
        for (int i = 0; i < 16; i++) { cst[i] = 0.0f; hs[i] = 0.0f; }
        for (int idx = tid; idx < 4352; idx += 256) { hhi[idx] = 0.0f; hlo[idx] = 0.0f; }
        __syncthreads();

        for (int t = 0; t < T_STEPS; t++) {
#pragma unroll
            for (int i = 0; i < 4; i++) {
                int idx = tid + i * 256;
                int r = idx >> 4, q = idx & 15;
                int n = n0 + r;
                float4 v = make_float4(0, 0, 0, 0);
                if (n < N_NODES)
                    v = *(const float4*)&h_all[((size_t)n * T_STEPS + t) * 64 + q * 4];
                int base = r * 68 + (q >> 1) * 8 + (q & 1);
                xs[base + 0] = __uint_as_float(tf32r(v.x));
                xs[base + 2] = __uint_as_float(tf32r(v.y));
                xs[base + 4] = __uint_as_float(tf32r(v.z));
                xs[base + 6] = __uint_as_float(tf32r(v.w));
            }
            __syncthreads();

            float acc[4][4][4];   // [mt][gate][4]
#pragma unroll
            for (int mt = 0; mt < 4; mt++)
#pragma unroll
                for (int g = 0; g < 4; g++)
#pragma unroll
                    for (int c = 0; c < 4; c++) acc[mt][g][c] = 0.0f;

#pragma unroll
            for (int pass = 0; pass < 3; pass++) {
                const float* A = (pass == 0) ? xs : (pass == 1) ? hhi : hlo;
                const float* W = (pass == 0) ? sWi : sWh;
#pragma unroll
                for (int ks = 0; ks < 8; ks++) {
                    float2 af0[4], af1[4];
#pragma unroll
                    for (int mt = 0; mt < 4; mt++) {
                        af0[mt] = *(float2*)&A[(mt * 16 + gid) * 68 + ks * 8 + tig * 2];
                        af1[mt] = *(float2*)&A[(mt * 16 + gid + 8) * 68 + ks * 8 + tig * 2];
                    }
#pragma unroll
                    for (int g = 0; g < 4; g++) {
                        float2 bwv = *(float2*)&W[(g * 64 + w * 8 + gid) * 68 + ks * 8 + tig * 2];
#pragma unroll
                        for (int mt = 0; mt < 4; mt++)
                            asm volatile(
                                "mma.sync.aligned.m16n8k8.row.col.f32.tf32.tf32.f32 "
                                "{%0,%1,%2,%3}, {%4,%5,%6,%7}, {%8,%9}, {%0,%1,%2,%3};"
                                : "+f"(acc[mt][g][0]), "+f"(acc[mt][g][1]),
                                  "+f"(acc[mt][g][2]), "+f"(acc[mt][g][3])
                                : "r"(__float_as_uint(af0[mt].x)), "r"(__float_as_uint(af1[mt].x)),
                                  "r"(__float_as_uint(af0[mt].y)), "r"(__float_as_uint(af1[mt].y)),
                                  "r"(__float_as_uint(bwv.x)), "r"(__float_as_uint(bwv.y)));
                    }
                }
            }

#pragma unroll
            for (int mt = 0; mt < 4; mt++) {
#pragma unroll
                for (int j = 0; j < 4; j++) {
                    float gi = acc[mt][0][j] + ((j & 1) ? bi1 : bi0);
                    float gf = acc[mt][1][j] + ((j & 1) ? bf1 : bf0);
                    float gg = acc[mt][2][j] + ((j & 1) ? bg1 : bg0);
                    float go = acc[mt][3][j] + ((j & 1) ? bo1 : bo0);
                    int ci = mt * 4 + j;
                    float cn = sigf(gf) * cst[ci] + sigf(gi) * tanhfast(gg);
                    float hv = sigf(go) * tanhfast(cn);
                    cst[ci] = cn;
                    hs[ci] += hv;
                    int row = mt * 16 + gid + ((j >> 1) ? 8 : 0);
                    float hi = __uint_as_float(tf32r(hv));
                    int slot = row * 68 + w * 8 + ((j & 1) ? p1 : p0);
                    hhi[slot] = hi;
                    hlo[slot] = __uint_as_float(tf32r(hv - hi));
                }
            }
            __syncthreads();
        }

#pragma unroll
        for (int mt = 0; mt < 4; mt++) {
#pragma unroll
            for (int jr = 0; jr < 2; jr++) {
                int row = mt * 16 + gid + jr * 8;
                int n = n0 + row;
                if (n < N_NODES)
                    *(float2*)&out_ht[n * 64 + u0] =
                        make_float2(hs[mt * 4 + jr * 2] * inv, hs[mt * 4 + jr * 2 + 1] * inv);
            }
        }
        __syncthreads();
    }
}

__global__ void k_join_anchor() {}

// ---------------- launch ------------------------------------------------------
extern "C" void kernel_launch(void* const* d_in, const int* in_sizes, int n_in,
                              void* d_out, int out_size) {
    const float* h     = (const float*)d_in[0];
    const int*   src   = (const int*)d_in[1];
    const int*   dst   = (const int*)d_in[2];
    const float* gamma = (const float*)d_in[3];
    const float* beta  = (const float*)d_in[4];
    const float* W0    = (const float*)d_in[5];
    const float* b0    = (const float*)d_in[6];
    const float* W1    = (const float*)d_in[7];
    const float* b1    = (const float*)d_in[8];
    const float* Wih   = (const float*)d_in[9];
    const float* Whh   = (const float*)d_in[10];
    const float* bih   = (const float*)d_in[11];
    const float* bhh   = (const float*)d_in[12];
    float* out = (float*)d_out;
    (void)in_sizes; (void)n_in;

    // one-time resource setup OUTSIDE graph capture
    static cudaStream_t s1 = 0;
    static cudaEvent_t eFork = 0, eNorm = 0, eGemm = 0, eJoin = 0;
    static int multi = -1;
    if (multi < 0) {
        bool ok = (cudaStreamCreateWithFlags(&s1, cudaStreamNonBlocking) == cudaSuccess);
        if (ok) ok = (cudaEventCreateWithFlags(&eFork, cudaEventDisableTiming) == cudaSuccess);
        if (ok) ok = (cudaEventCreateWithFlags(&eNorm, cudaEventDisableTiming) == cudaSuccess);
        if (ok) ok = (cudaEventCreateWithFlags(&eGemm, cudaEventDisableTiming) == cudaSuccess);
        if (ok) ok = (cudaEventCreateWithFlags(&eJoin, cudaEventDisableTiming) == cudaSuccess);
        cudaFuncSetAttribute(k_lstm_fused, cudaFuncAttributeMaxDynamicSharedMemorySize,
                             LSTM_SMEM_BYTES);
        multi = ok ? 1 : 0;
    }
    cudaStream_t sg = multi ? s1 : (cudaStream_t)0;

    // stream 0: init -> fork -> BN -> prepall -> (wait norm) gemm -> LSTM
    k_init<<<512, 256>>>(out, out_size);
    if (multi) {
        cudaEventRecord(eFork, 0);
        cudaStreamWaitEvent(sg, eFork, 0);
    }
    k_bnstats<<<1184, 256>>>((const float4*)h);
    k_prepall<<<33, 256>>>(gamma, beta, W0, Wih, Whh, bih, bhh);

    // sg: graph structure (concurrent with BN/prep when multi)
    k_deg<<<800, 256, 0, sg>>>(src, dst);
    k_norm<<<128, 256, 0, sg>>>();
    if (multi) {
        cudaEventRecord(eNorm, sg);
        cudaStreamWaitEvent(0, eNorm, 0);   // gemm needs g_outnorm
    }
    k_scan<<<1, 1024, 0, sg>>>();
    k_csr<<<800, 256, 0, sg>>>(src, dst);

    // stream 0: gemm (full chip), then persistent LSTM
    k_gemm_b<<<592, 256, 0, 0>>>(h);
    if (multi) {
        cudaEventRecord(eGemm, 0);
        cudaStreamWaitEvent(sg, eGemm, 0);  // gathers need M1
    }
    k_lstm_fused<<<148, 256, LSTM_SMEM_BYTES>>>(h, out + T_STEPS * 64);

    // sg: gathers
    k_gatherA<<<1184, 256, 0, sg>>>(W1, b0);
    k_gatherB<<<1184, 256, 0, sg>>>(b1, out);

    if (multi) {
        cudaEventRecord(eJoin, sg);
        cudaStreamWaitEvent(0, eJoin, 0);
        k_join_anchor<<<1, 1, 0, 0>>>();
    }
}

// round 17
// speedup vs baseline: 1.1525x; 1.0992x over previous
#include <cuda_runtime.h>
#include <cuda_bf16.h>
#include <math.h>
#include <stdint.h>

#define N_NODES 50000
#define T_STEPS 24
#define E_EDGES 800000
#define NT_ROWS (N_NODES * T_STEPS)

typedef unsigned long long ull;

// ---------------- packed helpers ---------------------------------------------
__device__ __forceinline__ ull ffma2(ull a, ull b, ull c) {
    ull d;
    asm("fma.rn.f32x2 %0, %1, %2, %3;" : "=l"(d) : "l"(a), "l"(b), "l"(c));
    return d;
}
__device__ __forceinline__ ull dup2f(float x) {
    ull r; asm("mov.b64 %0, {%1, %1};" : "=l"(r) : "f"(x)); return r;
}
__device__ __forceinline__ ull pack2f(float x, float y) {
    ull r; asm("mov.b64 %0, {%1, %2};" : "=l"(r) : "f"(x), "f"(y)); return r;
}
__device__ __forceinline__ float2 unpack2(ull v) {
    float2 r; asm("mov.b64 {%0, %1}, %2;" : "=f"(r.x), "=f"(r.y) : "l"(v)); return r;
}
__device__ __forceinline__ unsigned bf2pack(float x, float y) {
    __nv_bfloat162 b = __float22bfloat162_rn(make_float2(x, y));
    return *(unsigned*)&b;
}
__device__ __forceinline__ float2 bf2unpack(unsigned u) {
    __nv_bfloat162 b = *(__nv_bfloat162*)&u;
    return __bfloat1622float2(b);
}
__device__ __forceinline__ unsigned tf32r(float f) {
    unsigned u; asm("cvt.rna.tf32.f32 %0, %1;" : "=r"(u) : "f"(f)); return u;
}
// fast sigmoid/tanh: ex2.approx + rcp.approx (rel err ~1e-6)
__device__ __forceinline__ float sigf(float x) {
    float e, r;
    asm("ex2.approx.f32 %0, %1;" : "=f"(e) : "f"(-1.442695041f * x));
    asm("rcp.approx.f32 %0, %1;" : "=f"(r) : "f"(1.0f + e));
    return r;
}
__device__ __forceinline__ float tanhfast(float x) {
    return fmaf(2.0f, sigf(2.0f * x), -1.0f);
}

// ---------------- scratch (device globals) ----------------------------------
__device__ float g_sum[64];
__device__ float g_sumsq[64];
__device__ float g_bvec0[64];
__device__ float g_gbias[256];
__device__ unsigned g_Wg[256 * 64];     // tf32 bits of a*Wih, [g][k]
__device__ unsigned g_Whg[256 * 64];    // tf32 bits of Whh,   [g][k]
__device__ unsigned g_W0g[64 * 64];     // tf32 bits of a*W0,  [out][k]
__device__ float g_outnorm[N_NODES];
__device__ float g_innorm[N_NODES];
__device__ int   g_degout[N_NODES];
__device__ int   g_degin[N_NODES];
__device__ int   g_rowptr[N_NODES + 1];
__device__ int   g_cursor[N_NODES];
__device__ int   g_csrsrc[E_EDGES];
__device__ unsigned g_M1[T_STEPS * N_NODES * 32];
__device__ unsigned g_M2[T_STEPS * N_NODES * 32];
__device__ int   g_wq;
__device__ int   g_wqA;
__device__ int   g_wqB;

__device__ __forceinline__ float gelu_f(float x) {
    return 0.5f * x * (1.0f + erff(x * 0.70710678118654752440f));
}

// permuted k-slot within an 8-k block so (k, k+4) pairs are adjacent
__device__ __forceinline__ int kperm(int k) {   // k in 0..7
    return (k & 3) * 2 + (k >> 2);
}

// ---------------- init -------------------------------------------------------
__global__ void k_init(float* out, int out_n) {
    int i = blockIdx.x * blockDim.x + threadIdx.x;
    int stride = gridDim.x * blockDim.x;
    for (int j = i; j < out_n; j += stride) out[j] = 0.0f;
    for (int j = i; j < N_NODES; j += stride) { g_degout[j] = 0; g_degin[j] = 0; }
    if (i < 64) { g_sum[i] = 0.0f; g_sumsq[i] = 0.0f; }
    if (i == 0) { g_wq = 0; g_wqA = 0; g_wqB = 0; }
}

// ---------------- BN stats ---------------------------------------------------
__global__ void k_bnstats(const float4* __restrict__ h4) {
    __shared__ float ss[64], sq[64];
    int tid = threadIdx.x;
    if (tid < 64) { ss[tid] = 0.0f; sq[tid] = 0.0f; }
    __syncthreads();
    const int total4 = NT_ROWS * 16;
    float4 s = make_float4(0, 0, 0, 0);
    float4 q = make_float4(0, 0, 0, 0);
    for (int i = blockIdx.x * blockDim.x + tid; i < total4; i += gridDim.x * blockDim.x) {
        float4 v = h4[i];
        s.x += v.x; s.y += v.y; s.z += v.z; s.w += v.w;
        q.x += v.x * v.x; q.y += v.y * v.y; q.z += v.z * v.z; q.w += v.w * v.w;
    }
    int c = (tid & 15) * 4;
    atomicAdd(&ss[c + 0], s.x); atomicAdd(&ss[c + 1], s.y);
    atomicAdd(&ss[c + 2], s.z); atomicAdd(&ss[c + 3], s.w);
    atomicAdd(&sq[c + 0], q.x); atomicAdd(&sq[c + 1], q.y);
    atomicAdd(&sq[c + 2], q.z); atomicAdd(&sq[c + 3], q.w);
    __syncthreads();
    if (tid < 64) {
        atomicAdd(&g_sum[tid], ss[tid]);
        atomicAdd(&g_sumsq[tid], sq[tid]);
    }
}

// ---------------- merged prep ------------------------------------------------
__global__ void k_prepall(const float* __restrict__ gamma, const float* __restrict__ beta,
                          const float* __restrict__ W0,   const float* __restrict__ Wih,
                          const float* __restrict__ Whh,  const float* __restrict__ bih,
                          const float* __restrict__ bhh) {
    __shared__ float sa[64], sb[64];
    int tid = threadIdx.x;
    if (tid < 64) {
        float mu  = g_sum[tid]   * (1.0f / (float)NT_ROWS);
        float var = g_sumsq[tid] * (1.0f / (float)NT_ROWS) - mu * mu;
        float a = gamma[tid] * rsqrtf(var + 1e-5f);
        sa[tid] = a;
        sb[tid] = beta[tid] - mu * a;
    }
    __syncthreads();
    int b = blockIdx.x;
    if (b == 32) {
        for (int idx = tid; idx < 4096; idx += 256) {
            int out = idx >> 6, k = idx & 63;
            g_W0g[idx] = tf32r(sa[k] * W0[k * 64 + out]);
        }
        if (tid < 64) {
            float acc = 0.0f;
            for (int k = 0; k < 64; k++) acc += sb[k] * W0[k * 64 + tid];
            g_bvec0[tid] = acc;
        }
        {   // gate bias
            float acc = bih[tid] + bhh[tid];
            for (int k = 0; k < 64; k++) acc += sb[k] * Wih[tid * 64 + k];
            g_gbias[tid] = acc;
        }
    } else {
        for (int i = tid; i < 512; i += 256) {
            int idx = b * 512 + i;
            int g = idx >> 6, k = idx & 63;
            g_Wg[idx]  = tf32r(sa[k] * Wih[g * 64 + k]);
            g_Whg[idx] = tf32r(Whh[g * 64 + k]);
        }
    }
}

// ---------------- degrees / norms / CSR --------------------------------------
__global__ void k_deg(const int* __restrict__ src, const int* __restrict__ dst) {
    for (int e = blockIdx.x * blockDim.x + threadIdx.x; e < E_EDGES;
         e += gridDim.x * blockDim.x) {
        atomicAdd(&g_degout[src[e]], 1);
        atomicAdd(&g_degin[dst[e]], 1);
    }
}

__global__ void k_norm() {
    for (int n = blockIdx.x * blockDim.x + threadIdx.x; n < N_NODES;
         n += gridDim.x * blockDim.x) {
        g_outnorm[n] = rsqrtf(fmaxf((float)g_degout[n], 1.0f));
        g_innorm[n]  = rsqrtf(fmaxf((float)g_degin[n], 1.0f));
    }
}

__global__ void k_scan() {
    __shared__ int s[1024];
    const int CH = 49;
    int tid = threadIdx.x;
    int base = tid * CH;
    int tot = 0;
    for (int i = 0; i < CH; i++) {
        int idx = base + i;
        if (idx < N_NODES) tot += g_degin[idx];
    }
    s[tid] = tot;
    __syncthreads();
    for (int off = 1; off < 1024; off <<= 1) {
        int v = (tid >= off) ? s[tid - off] : 0;
        __syncthreads();
        s[tid] += v;
        __syncthreads();
    }
    int run = (tid > 0) ? s[tid - 1] : 0;
    for (int i = 0; i < CH; i++) {
        int idx = base + i;
        if (idx < N_NODES) {
            g_rowptr[idx] = run;
            g_cursor[idx] = run;
            run += g_degin[idx];
        } else if (idx == N_NODES) {
            g_rowptr[idx] = run;
        }
    }
}

__global__ void k_csr(const int* __restrict__ src, const int* __restrict__ dst) {
    for (int e = blockIdx.x * blockDim.x + threadIdx.x; e < E_EDGES;
         e += gridDim.x * blockDim.x) {
        int pos = atomicAdd(&g_cursor[dst[e]], 1);
        g_csrsrc[pos] = src[e];
    }
}

// ---------------- batched layer-1 GEMM via tf32 mma (R12 version) -------------
#define GEMM_TILES (782 * T_STEPS)
__global__ void __launch_bounds__(256) k_gemm_b(const float* __restrict__ X) {
    __shared__ __align__(16) float xs[64 * 68];
    __shared__ __align__(16) float sW[64 * 68];
    __shared__ float snorm[64];
    int tid = threadIdx.x, w = tid >> 5, lane = tid & 31;
    int gid = lane >> 2, tig = lane & 3;

    for (int idx = tid; idx < 4096; idx += 256) {
        int out = idx >> 6, k = idx & 63;
        sW[out * 68 + (k >> 3) * 8 + kperm(k & 7)] = __uint_as_float(g_W0g[idx]);
    }
    __syncthreads();
    float2 bw[8];
    {
        int col = w * 8 + gid;
#pragma unroll
        for (int ks = 0; ks < 8; ks++)
            bw[ks] = *(float2*)&sW[col * 68 + ks * 8 + tig * 2];
    }
    float bv0 = g_bvec0[w * 8 + tig * 2];
    float bv1 = g_bvec0[w * 8 + tig * 2 + 1];

    for (int tile = blockIdx.x; tile < GEMM_TILES; tile += gridDim.x) {
        int t = tile / 782;
        int n0 = (tile % 782) * 64;
#pragma unroll
        for (int i = 0; i < 4; i++) {
            int idx = tid + i * 256;
            int r = idx >> 4, q = idx & 15;
            int n = n0 + r;
            float4 v = make_float4(0, 0, 0, 0);
            if (n < N_NODES)
                v = *(const float4*)&X[((size_t)n * T_STEPS + t) * 64 + q * 4];
            int base = r * 68 + (q >> 1) * 8 + (q & 1);
            xs[base + 0] = __uint_as_float(tf32r(v.x));
            xs[base + 2] = __uint_as_float(tf32r(v.y));
            xs[base + 4] = __uint_as_float(tf32r(v.z));
            xs[base + 6] = __uint_as_float(tf32r(v.w));
        }
        if (tid < 64) {
            int n = n0 + tid;
            snorm[tid] = (n < N_NODES) ? g_outnorm[n] : 0.0f;
        }
        __syncthreads();

        float acc[4][4];
#pragma unroll
        for (int mt = 0; mt < 4; mt++)
#pragma unroll
            for (int c = 0; c < 4; c++) acc[mt][c] = 0.0f;

#pragma unroll
        for (int ks = 0; ks < 8; ks++) {
            float2 af0[4], af1[4];
#pragma unroll
            for (int mt = 0; mt < 4; mt++) {
                af0[mt] = *(float2*)&xs[(mt * 16 + gid) * 68 + ks * 8 + tig * 2];
                af1[mt] = *(float2*)&xs[(mt * 16 + gid + 8) * 68 + ks * 8 + tig * 2];
            }
#pragma unroll
            for (int mt = 0; mt < 4; mt++)
                asm volatile(
                    "mma.sync.aligned.m16n8k8.row.col.f32.tf32.tf32.f32 "
                    "{%0,%1,%2,%3}, {%4,%5,%6,%7}, {%8,%9}, {%0,%1,%2,%3};"
                    : "+f"(acc[mt][0]), "+f"(acc[mt][1]),
                      "+f"(acc[mt][2]), "+f"(acc[mt][3])
                    : "r"(__float_as_uint(af0[mt].x)), "r"(__float_as_uint(af1[mt].x)),
                      "r"(__float_as_uint(af0[mt].y)), "r"(__float_as_uint(af1[mt].y)),
                      "r"(__float_as_uint(bw[ks].x)), "r"(__float_as_uint(bw[ks].y)));
        }

        unsigned tb = (unsigned)t * N_NODES;
#pragma unroll
        for (int mt = 0; mt < 4; mt++) {
            int r0 = mt * 16 + gid;
            int n1 = n0 + r0, n2 = n1 + 8;
            if (n1 < N_NODES) {
                float sc = snorm[r0];
                g_M1[(tb + n1) * 32 + w * 4 + tig] =
                    bf2pack(sc * (acc[mt][0] + bv0), sc * (acc[mt][1] + bv1));
            }
            if (n2 < N_NODES) {
                float sc = snorm[r0 + 8];
                g_M1[(tb + n2) * 32 + w * 4 + tig] =
                    bf2pack(sc * (acc[mt][2] + bv0), sc * (acc[mt][3] + bv1));
            }
        }
        __syncthreads();
    }
}

// ---------------- gather layer1 (t-major queue; 8-wide MLP) -------------------
#define GTPT ((N_NODES + 127) / 128)        // 391
#define GTILES (GTPT * T_STEPS)             // 9384
__global__ void __launch_bounds__(256, 6) k_gatherA(const float* __restrict__ W1,
                                                    const float* __restrict__ b0) {
    __shared__ __align__(16) ull sW1p[64 * 32];
    __shared__ float sY[8][64];
    __shared__ int stile;
    int tid = threadIdx.x;
    int lane = tid & 31, w = tid >> 5;
    for (int idx = tid; idx < 2048; idx += 256) {
        int k = idx >> 5, c = idx & 31;
        float2 ww = *(const float2*)&W1[k * 64 + c * 2];
        sW1p[idx] = pack2f(ww.x, ww.y);
    }
    float bb0 = b0[2 * lane], bb1 = b0[2 * lane + 1];
    __syncthreads();

    for (;;) {
        if (tid == 0) stile = atomicAdd(&g_wqA, 1);
        __syncthreads();
        int tile = stile;
        if (tile >= GTILES) break;
        int t = tile / GTPT;
        int c0 = (tile % GTPT) * 128 + w * 16;
        unsigned base = (unsigned)t * N_NODES;

#pragma unroll 1
        for (int it = 0; it < 16; it++) {
            int v = c0 + it;
            if (v >= N_NODES) break;
            int s = g_rowptr[v], e = g_rowptr[v + 1];
            float a0 = 0.0f, a1 = 0.0f;
            int i = s;
            for (; i + 8 <= e; i += 8) {
                int u[8];
#pragma unroll
                for (int j = 0; j < 8; j++) u[j] = g_csrsrc[i + j];
                float2 m[8];
#pragma unroll
                for (int j = 0; j < 8; j++)
                    m[j] = bf2unpack(g_M1[(base + u[j]) * 32 + lane]);
                a0 += ((m[0].x + m[1].x) + (m[2].x + m[3].x))
                    + ((m[4].x + m[5].x) + (m[6].x + m[7].x));
                a1 += ((m[0].y + m[1].y) + (m[2].y + m[3].y))
                    + ((m[4].y + m[5].y) + (m[6].y + m[7].y));
            }
            for (; i + 4 <= e; i += 4) {
                int u0 = g_csrsrc[i + 0];
                int u1 = g_csrsrc[i + 1];
                int u2 = g_csrsrc[i + 2];
                int u3 = g_csrsrc[i + 3];
                float2 m0 = bf2unpack(g_M1[(base + u0) * 32 + lane]);
                float2 m1 = bf2unpack(g_M1[(base + u1) * 32 + lane]);
                float2 m2 = bf2unpack(g_M1[(base + u2) * 32 + lane]);
                float2 m3 = bf2unpack(g_M1[(base + u3) * 32 + lane]);
                a0 += (m0.x + m1.x) + (m2.x + m3.x);
                a1 += (m0.y + m1.y) + (m2.y + m3.y);
            }
            for (; i < e; i++) {
                int u = g_csrsrc[i];
                float2 m = bf2unpack(g_M1[(base + u) * 32 + lane]);
                a0 += m.x; a1 += m.y;
            }
            float inn = g_innorm[v];
            sY[w][2 * lane]     = gelu_f(a0 * inn + bb0);
            sY[w][2 * lane + 1] = gelu_f(a1 * inn + bb1);
            __syncwarp();
            ull acc = 0ull;
#pragma unroll 8
            for (int k = 0; k < 64; k++)
                acc = ffma2(dup2f(sY[w][k]), sW1p[k * 32 + lane], acc);
            float2 p = unpack2(acc);
            float sc = g_outnorm[v];
            g_M2[(base + v) * 32 + lane] = bf2pack(sc * p.x, sc * p.y);
            __syncwarp();
        }
        __syncthreads();
    }
}

// ---------------- gather layer2 + mean (t-major queue; 8-wide MLP) ------------
__global__ void __launch_bounds__(256, 6) k_gatherB(const float* __restrict__ b1,
                                                    float* __restrict__ out) {
    __shared__ float red[64];
    __shared__ int stile;
    int tid = threadIdx.x;
    int lane = tid & 31, w = tid >> 5;
    float bb0 = b1[2 * lane], bb1 = b1[2 * lane + 1];

    for (;;) {
        if (tid == 0) stile = atomicAdd(&g_wqB, 1);
        __syncthreads();
        int tile = stile;
        if (tile >= GTILES) break;
        int t = tile / GTPT;
        int c0 = (tile % GTPT) * 128 + w * 16;
        unsigned base = (unsigned)t * N_NODES;
        float acc0t = 0.0f, acc1t = 0.0f;

#pragma unroll 1
        for (int it = 0; it < 16; it++) {
            int v = c0 + it;
            if (v >= N_NODES) break;
            int s = g_rowptr[v], e = g_rowptr[v + 1];
            float a0 = 0.0f, a1 = 0.0f;
            int i = s;
            for (; i + 8 <= e; i += 8) {
                int u[8];
#pragma unroll
                for (int j = 0; j < 8; j++) u[j] = g_csrsrc[i + j];
                float2 m[8];
#pragma unroll
                for (int j = 0; j < 8; j++)
                    m[j] = bf2unpack(g_M2[(base + u[j]) * 32 + lane]);
                a0 += ((m[0].x + m[1].x) + (m[2].x + m[3].x))
                    + ((m[4].x + m[5].x) + (m[6].x + m[7].x));
                a1 += ((m[0].y + m[1].y) + (m[2].y + m[3].y))
                    + ((m[4].y + m[5].y) + (m[6].y + m[7].y));
            }
            for (; i + 4 <= e; i += 4) {
                int u0 = g_csrsrc[i + 0];
                int u1 = g_csrsrc[i + 1];
                int u2 = g_csrsrc[i + 2];
                int u3 = g_csrsrc[i + 3];
                float2 m0 = bf2unpack(g_M2[(base + u0) * 32 + lane]);
                float2 m1 = bf2unpack(g_M2[(base + u1) * 32 + lane]);
                float2 m2 = bf2unpack(g_M2[(base + u2) * 32 + lane]);
                float2 m3 = bf2unpack(g_M2[(base + u3) * 32 + lane]);
                a0 += (m0.x + m1.x) + (m2.x + m3.x);
                a1 += (m0.y + m1.y) + (m2.y + m3.y);
            }
            for (; i < e; i++) {
                int u = g_csrsrc[i];
                float2 m = bf2unpack(g_M2[(base + u) * 32 + lane]);
                a0 += m.x; a1 += m.y;
            }
            float inn = g_innorm[v];
            acc0t += gelu_f(a0 * inn + bb0);
            acc1t += gelu_f(a1 * inn + bb1);
        }
        if (tid < 64) red[tid] = 0.0f;
        __syncthreads();
        atomicAdd(&red[2 * lane + 0], acc0t);
        atomicAdd(&red[2 * lane + 1], acc1t);
        __syncthreads();
        if (tid < 64)
            atomicAdd(&out[t * 64 + tid], red[tid] * (1.0f / (float)N_NODES));
        __syncthreads();
    }
}

// ---------------- tensorized persistent LSTM (2-pass: x tf32 + h tf32) --------
// smem floats: xs 4352 | hhi 4352 | sWi 17408 | sWh 17408 = 43520
#define LSTM_SMEM_BYTES (43520 * 4)
__global__ void __launch_bounds__(256, 1) k_lstm_fused(
    const float* __restrict__ h_all, float* __restrict__ out_ht) {
    extern __shared__ float sm[];
    float* xs  = sm;              // [64][68]
    float* hhi = sm + 4352;
    float* sWi = sm + 8704;       // [256][68] perm layout
    float* sWh = sm + 26112;
    __shared__ int sgrp;

    int tid = threadIdx.x, w = tid >> 5, lane = tid & 31;
    int gid = lane >> 2, tig = lane & 3;

    for (int idx = tid; idx < 16384; idx += 256) {
        int col = idx >> 6, k = idx & 63;
        int slot = col * 68 + (k >> 3) * 8 + kperm(k & 7);
        sWi[slot] = __uint_as_float(g_Wg[idx]);
        sWh[slot] = __uint_as_float(g_Whg[idx]);
    }
    int u0 = w * 8 + tig * 2;
    float bi0 = g_gbias[u0],       bi1 = g_gbias[u0 + 1];
    float bf0 = g_gbias[64 + u0],  bf1 = g_gbias[64 + u0 + 1];
    float bg0 = g_gbias[128 + u0], bg1 = g_gbias[128 + u0 + 1];
    float bo0 = g_gbias[192 + u0], bo1 = g_gbias[192 + u0 + 1];
    int p0 = ((2 * tig) & 3) * 2 + (tig >> 1);
    int p1 = ((2 * tig + 1) & 3) * 2 + (tig >> 1);
    __syncthreads();

    const int NGROUPS = (N_NODES + 63) / 64;   // 782
    const float inv = 1.0f / (float)T_STEPS;

    for (;;) {
        if (tid == 0) sgrp = atomicAdd(&g_wq, 1);
        __syncthreads();
        int grp = sgrp;
        if (grp >= NGROUPS) break;
        int n0 = grp * 64;

        float cst[16], hs[16];
#pragma unroll
        for (int i = 0; i < 16; i++) { cst[i] = 0.0f; hs[i] = 0.0f; }
        for (int idx = tid; idx < 4352; idx += 256) hhi[idx] = 0.0f;
        __syncthreads();

        for (int t = 0; t < T_STEPS; t++) {
#pragma unroll
            for (int i = 0; i < 4; i++) {
                int idx = tid + i * 256;
                int r = idx >> 4, q = idx & 15;
                int n = n0 + r;
                float4 v = make_float4(0, 0, 0, 0);
                if (n < N_NODES)
                    v = *(const float4*)&h_all[((size_t)n * T_STEPS + t) * 64 + q * 4];
                int base = r * 68 + (q >> 1) * 8 + (q & 1);
                xs[base + 0] = __uint_as_float(tf32r(v.x));
                xs[base + 2] = __uint_as_float(tf32r(v.y));
                xs[base + 4] = __uint_as_float(tf32r(v.z));
                xs[base + 6] = __uint_as_float(tf32r(v.w));
            }
            __syncthreads();

            float acc[4][4][4];   // [mt][gate][4]
#pragma unroll
            for (int mt = 0; mt < 4; mt++)
#pragma unroll
                for (int g = 0; g < 4; g++)
#pragma unroll
                    for (int c = 0; c < 4; c++) acc[mt][g][c] = 0.0f;

#pragma unroll
            for (int pass = 0; pass < 2; pass++) {
                const float* A = (pass == 0) ? xs : hhi;
                const float* W = (pass == 0) ? sWi : sWh;
#pragma unroll
                for (int ks = 0; ks < 8; ks++) {
                    float2 af0[4], af1[4];
#pragma unroll
                    for (int mt = 0; mt < 4; mt++) {
                        af0[mt] = *(float2*)&A[(mt * 16 + gid) * 68 + ks * 8 + tig * 2];
                        af1[mt] = *(float2*)&A[(mt * 16 + gid + 8) * 68 + ks * 8 + tig * 2];
                    }
#pragma unroll
                    for (int g = 0; g < 4; g++) {
                        float2 bwv = *(float2*)&W[(g * 64 + w * 8 + gid) * 68 + ks * 8 + tig * 2];
#pragma unroll
                        for (int mt = 0; mt < 4; mt++)
                            asm volatile(
                                "mma.sync.aligned.m16n8k8.row.col.f32.tf32.tf32.f32 "
                                "{%0,%1,%2,%3}, {%4,%5,%6,%7}, {%8,%9}, {%0,%1,%2,%3};"
                                : "+f"(acc[mt][g][0]), "+f"(acc[mt][g][1]),
                                  "+f"(acc[mt][g][2]), "+f"(acc[mt][g][3])
                                : "r"(__float_as_uint(af0[mt].x)), "r"(__float_as_uint(af1[mt].x)),
                                  "r"(__float_as_uint(af0[mt].y)), "r"(__float_as_uint(af1[mt].y)),
                                  "r"(__float_as_uint(bwv.x)), "r"(__float_as_uint(bwv.y)));
                    }
                }
            }

#pragma unroll
            for (int mt = 0; mt < 4; mt++) {
#pragma unroll
                for (int j = 0; j < 4; j++) {
                    float gi = acc[mt][0][j] + ((j & 1) ? bi1 : bi0);
                    float gf = acc[mt][1][j] + ((j & 1) ? bf1 : bf0);
                    float gg = acc[mt][2][j] + ((j & 1) ? bg1 : bg0);
                    float go = acc[mt][3][j] + ((j & 1) ? bo1 : bo0);
                    int ci = mt * 4 + j;
                    float cn = sigf(gf) * cst[ci] + sigf(gi) * tanhfast(gg);
                    float hv = sigf(go) * tanhfast(cn);
                    cst[ci] = cn;
                    hs[ci] += hv;
                    int row = mt * 16 + gid + ((j >> 1) ? 8 : 0);
                    int slot = row * 68 + w * 8 + ((j & 1) ? p1 : p0);
                    hhi[slot] = __uint_as_float(tf32r(hv));
                }
            }
            __syncthreads();
        }

#pragma unroll
        for (int mt = 0; mt < 4; mt++) {
#pragma unroll
            for (int jr = 0; jr < 2; jr++) {
                int row = mt * 16 + gid + jr * 8;
                int n = n0 + row;
                if (n < N_NODES)
                    *(float2*)&out_ht[n * 64 + u0] =
                        make_float2(hs[mt * 4 + jr * 2] * inv, hs[mt * 4 + jr * 2 + 1] * inv);
            }
        }
        __syncthreads();
    }
}

__global__ void k_join_anchor() {}

// ---------------- launch ------------------------------------------------------
extern "C" void kernel_launch(void* const* d_in, const int* in_sizes, int n_in,
                              void* d_out, int out_size) {
    const float* h     = (const float*)d_in[0];
    const int*   src   = (const int*)d_in[1];
    const int*   dst   = (const int*)d_in[2];
    const float* gamma = (const float*)d_in[3];
    const float* beta  = (const float*)d_in[4];
    const float* W0    = (const float*)d_in[5];
    const float* b0    = (const float*)d_in[6];
    const float* W1    = (const float*)d_in[7];
    const float* b1    = (const float*)d_in[8];
    const float* Wih   = (const float*)d_in[9];
    const float* Whh   = (const float*)d_in[10];
    const float* bih   = (const float*)d_in[11];
    const float* bhh   = (const float*)d_in[12];
    float* out = (float*)d_out;
    (void)in_sizes; (void)n_in;

    // one-time resource setup OUTSIDE graph capture
    static cudaStream_t s1 = 0;
    static cudaEvent_t eFork = 0, eNorm = 0, eGemm = 0, eJoin = 0;
    static int multi = -1;
    if (multi < 0) {
        bool ok = (cudaStreamCreateWithFlags(&s1, cudaStreamNonBlocking) == cudaSuccess);
        if (ok) ok = (cudaEventCreateWithFlags(&eFork, cudaEventDisableTiming) == cudaSuccess);
        if (ok) ok = (cudaEventCreateWithFlags(&eNorm, cudaEventDisableTiming) == cudaSuccess);
        if (ok) ok = (cudaEventCreateWithFlags(&eGemm, cudaEventDisableTiming) == cudaSuccess);
        if (ok) ok = (cudaEventCreateWithFlags(&eJoin, cudaEventDisableTiming) == cudaSuccess);
        cudaFuncSetAttribute(k_lstm_fused, cudaFuncAttributeMaxDynamicSharedMemorySize,
                             LSTM_SMEM_BYTES);
        multi = ok ? 1 : 0;
    }
    cudaStream_t sg = multi ? s1 : (cudaStream_t)0;

    // stream 0: init -> fork -> BN -> prepall -> (wait norm) gemm -> LSTM
    k_init<<<512, 256>>>(out, out_size);
    if (multi) {
        cudaEventRecord(eFork, 0);
        cudaStreamWaitEvent(sg, eFork, 0);
    }
    k_bnstats<<<1184, 256>>>((const float4*)h);
    k_prepall<<<33, 256>>>(gamma, beta, W0, Wih, Whh, bih, bhh);

    // sg: graph structure (concurrent with BN/prep when multi)
    k_deg<<<800, 256, 0, sg>>>(src, dst);
    k_norm<<<128, 256, 0, sg>>>();
    if (multi) {
        cudaEventRecord(eNorm, sg);
        cudaStreamWaitEvent(0, eNorm, 0);   // gemm needs g_outnorm
    }
    k_scan<<<1, 1024, 0, sg>>>();
    k_csr<<<800, 256, 0, sg>>>(src, dst);

    // stream 0: gemm (full chip), then persistent LSTM
    k_gemm_b<<<592, 256, 0, 0>>>(h);
    if (multi) {
        cudaEventRecord(eGemm, 0);
        cudaStreamWaitEvent(sg, eGemm, 0);  // gathers need M1
    }
    k_lstm_fused<<<148, 256, LSTM_SMEM_BYTES>>>(h, out + T_STEPS * 64);

    // sg: gathers
    k_gatherA<<<1184, 256, 0, sg>>>(W1, b0);
    k_gatherB<<<1184, 256, 0, sg>>>(b1, out);

    if (multi) {
        cudaEventRecord(eJoin, sg);
        cudaStreamWaitEvent(0, eJoin, 0);
        k_join_anchor<<<1, 1, 0, 0>>>();
    }
}